// round 15
// baseline (speedup 1.0000x reference)
#include <cuda_runtime.h>
#include <cuda_bf16.h>
#include <math.h>
#include <stdint.h>

// Problem constants
#define Bc   2
#define Tc   1024
#define Dc   1024
#define Hc   16
#define HDc  64
#define FFc  4096
#define Lc   2
#define Vc   32000
#define BT   (Bc*Tc)
#define QKVN 3072

#define EPS_RMS 1.1920929e-07f
#define EPS_LN  1e-5f

// ------------------------- device scratch (static, no allocs) -------------
__device__ float    g_x  [BT*Dc];
__device__ float    g_qkv[BT*QKVN];
__device__ float    g_a  [BT*FFc];
// split-plane activations: [2][rows][K/2] packed bf16 k-pairs
__device__ uint32_t g_hsp[2*BT*(Dc/2)];
__device__ uint32_t g_osp[2*BT*(Dc/2)];
__device__ uint32_t g_asp[2*BT*(FFc/2)];
__device__ uint32_t g_msp[2*BT*(FFc/2)];
// split weights: [L][2][N][K/2]
__device__ uint32_t g_swqkv[(size_t)Lc*2*QKVN*(Dc/2)];
__device__ uint32_t g_swo  [(size_t)Lc*2*Dc*(Dc/2)];
__device__ uint32_t g_sf1  [(size_t)Lc*2*FFc*(Dc/2)];
__device__ uint32_t g_sfs  [(size_t)Lc*2*FFc*(FFc/2)];
__device__ uint32_t g_sf2  [(size_t)Lc*2*Dc*(FFc/2)];
__device__ uint32_t g_sout [(size_t)2*Vc*(Dc/2)];

// ------------------------- helpers ---------------------------------------
__device__ __forceinline__ float warpMax(float v) {
    #pragma unroll
    for (int o = 16; o; o >>= 1) v = fmaxf(v, __shfl_xor_sync(0xffffffffu, v, o));
    return v;
}
__device__ __forceinline__ float warpSum(float v) {
    #pragma unroll
    for (int o = 16; o; o >>= 1) v += __shfl_xor_sync(0xffffffffu, v, o);
    return v;
}
__device__ __forceinline__ void split2(float x0, float x1, uint32_t& hi, uint32_t& lo) {
    __nv_bfloat162 h = __floats2bfloat162_rn(x0, x1);
    float r0 = x0 - __bfloat162float(h.x);
    float r1 = x1 - __bfloat162float(h.y);
    __nv_bfloat162 l = __floats2bfloat162_rn(r0, r1);
    hi = *(uint32_t*)&h;
    lo = *(uint32_t*)&l;
}
__device__ __forceinline__ void mma_bf16(float* c, const uint32_t* a, const uint32_t* b) {
    asm volatile(
        "mma.sync.aligned.m16n8k16.row.col.f32.bf16.bf16.f32 "
        "{%0,%1,%2,%3}, {%4,%5,%6,%7}, {%8,%9}, {%0,%1,%2,%3};"
        : "+f"(c[0]), "+f"(c[1]), "+f"(c[2]), "+f"(c[3])
        : "r"(a[0]), "r"(a[1]), "r"(a[2]), "r"(a[3]),
          "r"(b[0]), "r"(b[1]));
}
__device__ __forceinline__ void ldsm_x4(uint32_t* r, uint32_t addr) {
    asm volatile("ldmatrix.sync.aligned.m8n8.x4.shared.b16 {%0,%1,%2,%3}, [%4];"
        : "=r"(r[0]), "=r"(r[1]), "=r"(r[2]), "=r"(r[3]) : "r"(addr));
}
__device__ __forceinline__ uint32_t smem_u32(const void* p) {
    uint32_t a;
    asm("{ .reg .u64 t; cvta.to.shared.u64 t, %1; cvt.u32.u64 %0, t; }"
        : "=r"(a) : "l"(p));
    return a;
}
__device__ __forceinline__ void cpa16(uint32_t dst, const void* src) {
    asm volatile("cp.async.cg.shared.global [%0], [%1], 16;"
        :: "r"(dst), "l"(src) : "memory");
}

// ------------------------- weight transpose+split -------------------------
// W [K][N] fp32 (layer z) -> S [2][N][K/2] packed bf16-pair planes
__global__ void wsplit_t(const float* __restrict__ W, uint32_t* __restrict__ S,
                         int K, int N, size_t lsw, size_t lss) {
    const float* Wl = W + (size_t)blockIdx.z * lsw;
    uint32_t*    Sl = S + (size_t)blockIdx.z * lss;
    int k0 = blockIdx.y * 64, n0 = blockIdx.x * 32;
    __shared__ float ts[64][33];
    int tid = threadIdx.x;
    #pragma unroll
    for (int i = 0; i < 8; i++) {
        int e = tid + i * 256;
        ts[e >> 5][e & 31] = Wl[(size_t)(k0 + (e >> 5)) * N + n0 + (e & 31)];
    }
    __syncthreads();
    size_t pl = (size_t)N * (K >> 1);
    #pragma unroll
    for (int i = 0; i < 4; i++) {
        int e = tid + i * 256;
        int nn = e >> 5, kp = e & 31;
        uint32_t hi, lo;
        split2(ts[2 * kp][nn], ts[2 * kp + 1][nn], hi, lo);
        size_t o = (size_t)(n0 + nn) * (K >> 1) + (k0 >> 1) + kp;
        Sl[o] = hi; Sl[pl + o] = lo;
    }
}

// qkv weights: [L][H][D][HD] -> merged [L][2][3072][512]; sec 0=q,1=k,2=v
__global__ void wsplit_qkv(const float* __restrict__ W, uint32_t* __restrict__ S, int sec) {
    int l = blockIdx.z >> 4, h = blockIdx.z & 15;
    const float* Wl = W + ((size_t)(l * Hc + h)) * Dc * HDc;
    uint32_t*    Sl = S + (size_t)l * 2 * QKVN * (Dc / 2);
    int k0 = blockIdx.y * 64, n0 = blockIdx.x * 32;
    __shared__ float ts[64][33];
    int tid = threadIdx.x;
    #pragma unroll
    for (int i = 0; i < 8; i++) {
        int e = tid + i * 256;
        ts[e >> 5][e & 31] = Wl[(size_t)(k0 + (e >> 5)) * HDc + n0 + (e & 31)];
    }
    __syncthreads();
    size_t pl = (size_t)QKVN * (Dc / 2);
    #pragma unroll
    for (int i = 0; i < 4; i++) {
        int e = tid + i * 256;
        int nn = e >> 5, kp = e & 31;
        uint32_t hi, lo;
        split2(ts[2 * kp][nn], ts[2 * kp + 1][nn], hi, lo);
        int nrow = sec * 1024 + h * HDc + n0 + nn;
        size_t o = (size_t)nrow * (Dc / 2) + (k0 >> 1) + kp;
        Sl[o] = hi; Sl[pl + o] = lo;
    }
}

// ------------------------- embedding gather -------------------------------
__global__ void embed_kernel(const int* __restrict__ idx, const float* __restrict__ emb) {
    int i = blockIdx.x * blockDim.x + threadIdx.x;
    if (i >= BT * Dc) return;
    int row = i >> 10;
    int d   = i & 1023;
    g_x[i] = emb[(size_t)idx[row] * Dc + d];
}

// ------------------------- RMSNorm -> split planes ------------------------
__global__ void rmsnorm_sp(const float* __restrict__ x, const float* __restrict__ w,
                           uint32_t* __restrict__ sp) {
    int row = blockIdx.x, tid = threadIdx.x;
    const float4* xr = (const float4*)(x + (size_t)row * Dc);
    float4 v = xr[tid];
    float ss = v.x*v.x + v.y*v.y + v.z*v.z + v.w*v.w;
    __shared__ float sred[8];
    ss = warpSum(ss);
    if ((tid & 31) == 0) sred[tid >> 5] = ss;
    __syncthreads();
    if (tid == 0) {
        float t = 0.f;
        #pragma unroll
        for (int i = 0; i < 8; i++) t += sred[i];
        sred[0] = rsqrtf(t * (1.0f / Dc) + EPS_RMS);
    }
    __syncthreads();
    float r = sred[0];
    float4 ww = ((const float4*)w)[tid];
    float y0 = v.x*r*ww.x, y1 = v.y*r*ww.y, y2 = v.z*r*ww.z, y3 = v.w*r*ww.w;
    size_t o = (size_t)row * (Dc/2) + tid * 2;
    size_t pl = (size_t)BT * (Dc/2);
    uint32_t hi, lo;
    split2(y0, y1, hi, lo); sp[o]   = hi; sp[pl+o]   = lo;
    split2(y2, y3, hi, lo); sp[o+1] = hi; sp[pl+o+1] = lo;
}

// ------------------------- LayerNorm -> split planes ----------------------
__global__ void layernorm_sp(const float* __restrict__ x, const float* __restrict__ w,
                             const float* __restrict__ b, uint32_t* __restrict__ sp) {
    int row = blockIdx.x, tid = threadIdx.x;
    const float4* xr = (const float4*)(x + (size_t)row * Dc);
    float4 v = xr[tid];
    __shared__ float sred[8];
    __shared__ float sbc[2];
    float s = v.x + v.y + v.z + v.w;
    s = warpSum(s);
    if ((tid & 31) == 0) sred[tid >> 5] = s;
    __syncthreads();
    if (tid == 0) {
        float t = 0.f;
        #pragma unroll
        for (int i = 0; i < 8; i++) t += sred[i];
        sbc[0] = t * (1.0f / Dc);
    }
    __syncthreads();
    float mu = sbc[0];
    float d0 = v.x-mu, d1 = v.y-mu, d2 = v.z-mu, d3 = v.w-mu;
    float sq = d0*d0 + d1*d1 + d2*d2 + d3*d3;
    sq = warpSum(sq);
    if ((tid & 31) == 0) sred[tid >> 5] = sq;
    __syncthreads();
    if (tid == 0) {
        float t = 0.f;
        #pragma unroll
        for (int i = 0; i < 8; i++) t += sred[i];
        sbc[1] = rsqrtf(t * (1.0f / Dc) + EPS_LN);
    }
    __syncthreads();
    float r = sbc[1];
    float4 ww = ((const float4*)w)[tid];
    float4 bb = ((const float4*)b)[tid];
    float y0 = d0*r*ww.x + bb.x, y1 = d1*r*ww.y + bb.y;
    float y2 = d2*r*ww.z + bb.z, y3 = d3*r*ww.w + bb.w;
    size_t o = (size_t)row * (Dc/2) + tid * 2;
    size_t pl = (size_t)BT * (Dc/2);
    uint32_t hi, lo;
    split2(y0, y1, hi, lo); sp[o]   = hi; sp[pl+o]   = lo;
    split2(y2, y3, hi, lo); sp[o+1] = hi; sp[pl+o+1] = lo;
}

// ------------------------- tiled flash attention --------------------------
// grid (T/8, B*H), 256 thr; warp w handles q row t0+w.
// qkv: [B*T][3072] fp32 (q|k|v). Writes o as split planes [2][BT][Dc/2].
__global__ void __launch_bounds__(256) attn_kernel(const float* __restrict__ qkv,
                                                   uint32_t* __restrict__ osp) {
    __shared__ float Ks[64][68];
    __shared__ float Vs[64][68];
    __shared__ float qs[8][68];
    int tid = threadIdx.x, wid = tid >> 5, lane = tid & 31;
    int bh = blockIdx.y, b = bh >> 4, h = bh & 15;
    int t0 = blockIdx.x << 3;
    int t = t0 + wid;
    const float* base = qkv + (size_t)b * Tc * QKVN;

    if (tid < 128) {
        int r = tid >> 4, c4 = tid & 15;
        const float4* src = (const float4*)(base + (size_t)(t0 + r) * QKVN + h * HDc);
        *(float4*)&qs[r][c4 * 4] = src[c4];
    }

    float m = -INFINITY, l = 0.f, o0 = 0.f, o1 = 0.f;
    int nCh = ((t0 + 7) >> 6) + 1;

    for (int ch = 0; ch < nCh; ch++) {
        int sb = ch << 6;
        __syncthreads();
        #pragma unroll
        for (int i = 0; i < 4; i++) {
            int e = tid + i * 256;
            int r = e >> 4, c4 = e & 15;
            const float* rowp = base + (size_t)(sb + r) * QKVN + h * HDc;
            *(float4*)&Ks[r][c4 * 4] = ((const float4*)(rowp + Dc))[c4];
            *(float4*)&Vs[r][c4 * 4] = ((const float4*)(rowp + 2 * Dc))[c4];
        }
        __syncthreads();

        float sc0 = 0.f, sc1 = 0.f;
        const float4* q4  = (const float4*)qs[wid];
        const float4* k40 = (const float4*)Ks[lane];
        const float4* k41 = (const float4*)Ks[lane + 32];
        #pragma unroll
        for (int d = 0; d < 16; d++) {
            float4 qv = q4[d], ka = k40[d], kb = k41[d];
            sc0 += qv.x*ka.x + qv.y*ka.y + qv.z*ka.z + qv.w*ka.w;
            sc1 += qv.x*kb.x + qv.y*kb.y + qv.z*kb.z + qv.w*kb.w;
        }
        sc0 = (sb + lane      <= t) ? sc0 * 0.125f : -INFINITY;
        sc1 = (sb + 32 + lane <= t) ? sc1 * 0.125f : -INFINITY;

        float mch  = warpMax(fmaxf(sc0, sc1));
        float mnew = fmaxf(m, mch);
        float alpha = __expf(m - mnew);
        float p0 = __expf(sc0 - mnew);
        float p1 = __expf(sc1 - mnew);
        l = l * alpha + warpSum(p0 + p1);
        o0 *= alpha; o1 *= alpha;
        m = mnew;
        #pragma unroll
        for (int s = 0; s < 32; s++) {
            float p = __shfl_sync(0xffffffffu, p0, s);
            float2 vv = *(const float2*)&Vs[s][lane * 2];
            o0 += p * vv.x; o1 += p * vv.y;
        }
        #pragma unroll
        for (int s = 0; s < 32; s++) {
            float p = __shfl_sync(0xffffffffu, p1, s);
            float2 vv = *(const float2*)&Vs[s + 32][lane * 2];
            o0 += p * vv.x; o1 += p * vv.y;
        }
    }

    float inv = 1.0f / l;
    uint32_t hi, lo;
    split2(o0 * inv, o1 * inv, hi, lo);
    size_t orow = (size_t)(b * Tc + t) * (Dc/2) + h * 32 + lane;
    osp[orow] = hi;
    osp[(size_t)BT * (Dc/2) + orow] = lo;
}

// ------------------------- bf16x3 mma.sync GEMM ---------------------------
// C = A @ B: Asp [2][M][K/2], Bsp [2][N][K/2]. Tile 128xTN, BK=32,
// 3-stage cp.async pipeline, ldmatrix fragments, 8 warps.
#define F_F32  1
#define F_RES  2
#define F_SPL  4
#define F_SILU 8

__device__ __forceinline__ uint32_t swz_addr(int row, int c) {
    return (uint32_t)(row * 64 + ((c * 16) ^ (((row >> 1) & 3) << 4)));
}

template<int TN>
__device__ __forceinline__ void tc_gemm_body(
    const uint32_t* __restrict__ Asp, const uint32_t* __restrict__ Bsp,
    const float* __restrict__ bias, float* __restrict__ Cf,
    uint32_t* __restrict__ Csp, const float* __restrict__ Aux,
    int M, int N, int K, int flags)
{
    constexpr int MI = (TN == 256) ? 4 : 2;
    constexpr int BPL = TN * 64;               // B plane bytes per stage
    constexpr int OPA_H = 0, OPA_L = 8192;
    constexpr int OPB_H = 16384;
    constexpr int OPB_L = 16384 + BPL;
    constexpr int STG   = 16384 + 2 * BPL;

    extern __shared__ char smem[];
    uint32_t smem0 = smem_u32(smem);
    int tid = threadIdx.x, wid = tid >> 5, lane = tid & 31;
    int m0 = blockIdx.y << 7, n0 = blockIdx.x * TN;
    int Kh = K >> 1;
    size_t planeA = (size_t)M * Kh, planeB = (size_t)N * Kh;
    const uint32_t* Ag = Asp + (size_t)m0 * Kh;
    const uint32_t* Bg = Bsp + (size_t)n0 * Kh;
    int nCh = K >> 5;

    int r0 = tid >> 2, c0 = tid & 3;

    auto load_st = [&](int ch, int st) {
        uint32_t sb = smem0 + st * STG;
        int kofs = ch * 16 + c0 * 4;
        const uint32_t* a0 = Ag + (size_t)r0 * Kh + kofs;
        const uint32_t* a1 = Ag + (size_t)(r0 + 64) * Kh + kofs;
        uint32_t s0 = swz_addr(r0, c0), s1 = swz_addr(r0 + 64, c0);
        cpa16(sb + OPA_H + s0, a0);
        cpa16(sb + OPA_H + s1, a1);
        cpa16(sb + OPA_L + s0, a0 + planeA);
        cpa16(sb + OPA_L + s1, a1 + planeA);
        #pragma unroll
        for (int rb = 0; rb < TN / 64; rb++) {
            int rr = r0 + rb * 64;
            const uint32_t* bp = Bg + (size_t)rr * Kh + kofs;
            uint32_t ss = swz_addr(rr, c0);
            cpa16(sb + OPB_H + ss, bp);
            cpa16(sb + OPB_L + ss, bp + planeB);
        }
        asm volatile("cp.async.commit_group;" ::: "memory");
    };

    float acc[MI][8][4];
    #pragma unroll
    for (int i = 0; i < MI; i++)
        #pragma unroll
        for (int j = 0; j < 8; j++)
            #pragma unroll
            for (int r = 0; r < 4; r++) acc[i][j][r] = 0.f;

    int wm, wn;
    if (TN == 256) { wm = (wid & 1) << 6; wn = (wid >> 1) << 6; }
    else           { wm = (wid & 3) << 5; wn = (wid >> 2) << 6; }
    int lrow = lane & 15, lhalf = lane >> 4;

    load_st(0, 0);
    load_st(1, 1);

    for (int ch = 0; ch < nCh; ch++) {
        if (ch + 2 < nCh) {
            asm volatile("cp.async.wait_group 1;" ::: "memory");
        } else {
            asm volatile("cp.async.wait_group 0;" ::: "memory");
        }
        __syncthreads();
        uint32_t sb = smem0 + (ch % 3) * STG;
        #pragma unroll
        for (int ks = 0; ks < 2; ks++) {
            int c = ks * 2 + lhalf;
            uint32_t ah[MI][4], al[MI][4], bq[4][4];
            #pragma unroll
            for (int i = 0; i < MI; i++) {
                int row = wm + i * 16 + lrow;
                uint32_t sa = swz_addr(row, c);
                ldsm_x4(ah[i], sb + OPA_H + sa);
                ldsm_x4(al[i], sb + OPA_L + sa);
            }
            #pragma unroll
            for (int jj = 0; jj < 4; jj++)
                ldsm_x4(bq[jj], sb + OPB_H + swz_addr(wn + jj * 16 + lrow, c));
            #pragma unroll
            for (int jj = 0; jj < 4; jj++) {
                uint32_t bf0[2] = {bq[jj][0], bq[jj][2]};
                uint32_t bf1[2] = {bq[jj][1], bq[jj][3]};
                #pragma unroll
                for (int i = 0; i < MI; i++) {
                    mma_bf16(acc[i][2*jj],   ah[i], bf0);
                    mma_bf16(acc[i][2*jj+1], ah[i], bf1);
                    mma_bf16(acc[i][2*jj],   al[i], bf0);
                    mma_bf16(acc[i][2*jj+1], al[i], bf1);
                }
            }
            #pragma unroll
            for (int jj = 0; jj < 4; jj++)
                ldsm_x4(bq[jj], sb + OPB_L + swz_addr(wn + jj * 16 + lrow, c));
            #pragma unroll
            for (int jj = 0; jj < 4; jj++) {
                uint32_t bf0[2] = {bq[jj][0], bq[jj][2]};
                uint32_t bf1[2] = {bq[jj][1], bq[jj][3]};
                #pragma unroll
                for (int i = 0; i < MI; i++) {
                    mma_bf16(acc[i][2*jj],   ah[i], bf0);
                    mma_bf16(acc[i][2*jj+1], ah[i], bf1);
                }
            }
        }
        if (ch + 2 < nCh) load_st(ch + 2, (ch + 2) % 3);
    }

    // epilogue
    int erow = lane >> 2;
    int ecol = (lane & 3) * 2;
    size_t splPl = (size_t)M * (N >> 1);
    #pragma unroll
    for (int i = 0; i < MI; i++) {
        int row = m0 + wm + i * 16 + erow;
        #pragma unroll
        for (int j = 0; j < 8; j++) {
            int col = n0 + wn + j * 8 + ecol;
            float b0 = 0.f, b1 = 0.f;
            if (bias) { b0 = bias[col]; b1 = bias[col + 1]; }
            float v00 = acc[i][j][0] + b0, v01 = acc[i][j][1] + b1;
            float v10 = acc[i][j][2] + b0, v11 = acc[i][j][3] + b1;
            size_t o0 = (size_t)row * N + col;
            size_t o1 = (size_t)(row + 8) * N + col;
            if (flags & F_SILU) {
                float a00 = Aux[o0], a01 = Aux[o0 + 1];
                float a10 = Aux[o1], a11 = Aux[o1 + 1];
                v00 *= a00 / (1.0f + expf(-a00));
                v01 *= a01 / (1.0f + expf(-a01));
                v10 *= a10 / (1.0f + expf(-a10));
                v11 *= a11 / (1.0f + expf(-a11));
            }
            if (flags & F_RES) {
                v00 += Cf[o0]; v01 += Cf[o0 + 1];
                v10 += Cf[o1]; v11 += Cf[o1 + 1];
            }
            if (flags & F_F32) {
                Cf[o0] = v00; Cf[o0 + 1] = v01;
                Cf[o1] = v10; Cf[o1 + 1] = v11;
            }
            if (flags & F_SPL) {
                size_t p0 = (size_t)row * (N >> 1) + (col >> 1);
                size_t p1 = (size_t)(row + 8) * (N >> 1) + (col >> 1);
                uint32_t hi, lo;
                split2(v00, v01, hi, lo); Csp[p0] = hi; Csp[splPl + p0] = lo;
                split2(v10, v11, hi, lo); Csp[p1] = hi; Csp[splPl + p1] = lo;
            }
        }
    }
}

__global__ void __launch_bounds__(256, 2) tc_gemm128(
    const uint32_t* __restrict__ Asp, const uint32_t* __restrict__ Bsp,
    const float* __restrict__ bias, float* __restrict__ Cf,
    uint32_t* __restrict__ Csp, const float* __restrict__ Aux,
    int M, int N, int K, int flags)
{
    tc_gemm_body<128>(Asp, Bsp, bias, Cf, Csp, Aux, M, N, K, flags);
}

__global__ void __launch_bounds__(256, 1) tc_gemm256(
    const uint32_t* __restrict__ Asp, const uint32_t* __restrict__ Bsp,
    const float* __restrict__ bias, float* __restrict__ Cf,
    uint32_t* __restrict__ Csp, const float* __restrict__ Aux,
    int M, int N, int K, int flags)
{
    tc_gemm_body<256>(Asp, Bsp, bias, Cf, Csp, Aux, M, N, K, flags);
}

#define SMEM128 (3 * (16384 + 2 * 128 * 64))
#define SMEM256 (3 * (16384 + 2 * 256 * 64))

// ------------------------- host orchestration -----------------------------
extern "C" void kernel_launch(void* const* d_in, const int* in_sizes, int n_in,
                              void* d_out, int out_size) {
    const int*   idx    = (const int*)  d_in[0];
    const float* emb    = (const float*)d_in[1];
    const float* wq     = (const float*)d_in[2];
    const float* wk     = (const float*)d_in[3];
    const float* wv     = (const float*)d_in[4];
    const float* attn_w = (const float*)d_in[5];
    const float* attn_b = (const float*)d_in[6];
    const float* n1_w   = (const float*)d_in[7];
    const float* n2_w   = (const float*)d_in[8];
    const float* f1_w   = (const float*)d_in[9];
    const float* f1_b   = (const float*)d_in[10];
    const float* fs_w   = (const float*)d_in[11];
    const float* fs_b   = (const float*)d_in[12];
    const float* f2_w   = (const float*)d_in[13];
    const float* f2_b   = (const float*)d_in[14];
    const float* ln_w   = (const float*)d_in[15];
    const float* ln_b   = (const float*)d_in[16];
    const float* out_w  = (const float*)d_in[17];
    const float* out_b  = (const float*)d_in[18];

    float *x, *qkv, *a;
    uint32_t *hsp, *osp, *asp, *msp;
    uint32_t *swqkv, *swo, *sf1, *sfs, *sf2, *sout;
    cudaGetSymbolAddress((void**)&x,    g_x);
    cudaGetSymbolAddress((void**)&qkv,  g_qkv);
    cudaGetSymbolAddress((void**)&a,    g_a);
    cudaGetSymbolAddress((void**)&hsp,  g_hsp);
    cudaGetSymbolAddress((void**)&osp,  g_osp);
    cudaGetSymbolAddress((void**)&asp,  g_asp);
    cudaGetSymbolAddress((void**)&msp,  g_msp);
    cudaGetSymbolAddress((void**)&swqkv,g_swqkv);
    cudaGetSymbolAddress((void**)&swo,  g_swo);
    cudaGetSymbolAddress((void**)&sf1,  g_sf1);
    cudaGetSymbolAddress((void**)&sfs,  g_sfs);
    cudaGetSymbolAddress((void**)&sf2,  g_sf2);
    cudaGetSymbolAddress((void**)&sout, g_sout);

    cudaFuncSetAttribute(tc_gemm128,
                         cudaFuncAttributeMaxDynamicSharedMemorySize, SMEM128);
    cudaFuncSetAttribute(tc_gemm256,
                         cudaFuncAttributeMaxDynamicSharedMemorySize, SMEM256);

    dim3 gQKV(QKVN/256, BT/128);
    dim3 gD(Dc/128, BT/128);
    dim3 gF(FFc/256, BT/128);
    dim3 gV(Vc/256, BT/128);

    // ---- ordered so the 6th kernel (ncu -s 5) is the first QKV GEMM ----
    embed_kernel<<<(BT * Dc) / 256, 256>>>(idx, emb);                       // 0
    wsplit_qkv<<<dim3(2, 16, Lc * Hc), 256>>>(wq, swqkv, 0);                // 1
    wsplit_qkv<<<dim3(2, 16, Lc * Hc), 256>>>(wk, swqkv, 1);                // 2
    wsplit_qkv<<<dim3(2, 16, Lc * Hc), 256>>>(wv, swqkv, 2);                // 3
    rmsnorm_sp<<<BT, 256>>>(x, n1_w, hsp);                                  // 4
    tc_gemm256<<<gQKV, 256, SMEM256>>>(hsp, swqkv, nullptr, qkv, nullptr,
                                       nullptr, BT, QKVN, Dc, F_F32);       // 5 (ncu)

    // remaining weight splits (all layers)
    wsplit_t<<<dim3(Dc/32,  Dc/64,  Lc), 256>>>(attn_w, swo, Dc,  Dc,
        (size_t)Dc*Dc,   (size_t)2*Dc*(Dc/2));
    wsplit_t<<<dim3(FFc/32, Dc/64,  Lc), 256>>>(f1_w,   sf1, Dc,  FFc,
        (size_t)Dc*FFc,  (size_t)2*FFc*(Dc/2));
    wsplit_t<<<dim3(FFc/32, FFc/64, Lc), 256>>>(fs_w,   sfs, FFc, FFc,
        (size_t)FFc*FFc, (size_t)2*FFc*(FFc/2));
    wsplit_t<<<dim3(Dc/32,  FFc/64, Lc), 256>>>(f2_w,   sf2, FFc, Dc,
        (size_t)FFc*Dc,  (size_t)2*Dc*(FFc/2));
    wsplit_t<<<dim3(Vc/32,  Dc/64,  1),  256>>>(out_w,  sout, Dc, Vc, 0, 0);

    for (int l = 0; l < Lc; l++) {
        uint32_t* wqkv_l = swqkv + (size_t)l * 2 * QKVN * (Dc/2);
        uint32_t* swo_l  = swo   + (size_t)l * 2 * Dc   * (Dc/2);
        uint32_t* sf1_l  = sf1   + (size_t)l * 2 * FFc  * (Dc/2);
        uint32_t* sfs_l  = sfs   + (size_t)l * 2 * FFc  * (FFc/2);
        uint32_t* sf2_l  = sf2   + (size_t)l * 2 * Dc   * (FFc/2);

        if (l > 0) {
            rmsnorm_sp<<<BT, 256>>>(x, n1_w + (size_t)l * Dc, hsp);
            tc_gemm256<<<gQKV, 256, SMEM256>>>(hsp, wqkv_l, nullptr, qkv,
                                               nullptr, nullptr, BT, QKVN, Dc, F_F32);
        }
        // rope diagonal is all-ones (theta = x // HD == 0): K unchanged.
        attn_kernel<<<dim3(Tc/8, Bc*Hc), 256>>>(qkv, osp);
        tc_gemm128<<<gD, 256, SMEM128>>>(osp, swo_l, attn_b + (size_t)l * Dc,
                                         x, nullptr, nullptr, BT, Dc, Dc,
                                         F_F32 | F_RES);

        rmsnorm_sp<<<BT, 256>>>(x, n2_w + (size_t)l * Dc, hsp);
        tc_gemm256<<<gF, 256, SMEM256>>>(hsp, sf1_l, f1_b + (size_t)l * FFc,
                                         a, asp, nullptr, BT, FFc, Dc,
                                         F_F32 | F_SPL);
        tc_gemm256<<<gF, 256, SMEM256>>>(asp, sfs_l, fs_b + (size_t)l * FFc,
                                         nullptr, msp, a, BT, FFc, FFc,
                                         F_SPL | F_SILU);
        tc_gemm128<<<gD, 256, SMEM128>>>(msp, sf2_l, f2_b + (size_t)l * Dc,
                                         x, nullptr, nullptr, BT, Dc, FFc,
                                         F_F32 | F_RES);
    }

    layernorm_sp<<<BT, 256>>>(x, ln_w, ln_b, hsp);
    tc_gemm256<<<gV, 256, SMEM256>>>(hsp, sout, out_b, (float*)d_out, nullptr,
                                     nullptr, BT, Vc, Dc, F_F32);
}

// round 16
// speedup vs baseline: 1.1033x; 1.1033x over previous
#include <cuda_runtime.h>
#include <cuda_bf16.h>
#include <math.h>
#include <stdint.h>

// Problem constants
#define Bc   2
#define Tc   1024
#define Dc   1024
#define Hc   16
#define HDc  64
#define FFc  4096
#define Lc   2
#define Vc   32000
#define BT   (Bc*Tc)
#define QKVN 3072

#define EPS_RMS 1.1920929e-07f
#define EPS_LN  1e-5f

// ------------------------- device scratch (static, no allocs) -------------
__device__ float    g_x  [BT*Dc];
__device__ float    g_qkv[BT*QKVN];
// split-plane activations: [2][rows][K/2] packed bf16 k-pairs
__device__ uint32_t g_hsp[2*BT*(Dc/2)];
__device__ uint32_t g_osp[2*BT*(Dc/2)];
__device__ uint32_t g_asp[2*BT*(FFc/2)];
__device__ uint32_t g_msp[2*BT*(FFc/2)];
// split weights: [L][2][N][K/2]
__device__ uint32_t g_swqkv[(size_t)Lc*2*QKVN*(Dc/2)];
__device__ uint32_t g_swo  [(size_t)Lc*2*Dc*(Dc/2)];
__device__ uint32_t g_sf1  [(size_t)Lc*2*FFc*(Dc/2)];
__device__ uint32_t g_sfs  [(size_t)Lc*2*FFc*(FFc/2)];
__device__ uint32_t g_sf2  [(size_t)Lc*2*Dc*(FFc/2)];
__device__ uint32_t g_sout [(size_t)2*Vc*(Dc/2)];

// ------------------------- helpers ---------------------------------------
__device__ __forceinline__ float warpMax(float v) {
    #pragma unroll
    for (int o = 16; o; o >>= 1) v = fmaxf(v, __shfl_xor_sync(0xffffffffu, v, o));
    return v;
}
__device__ __forceinline__ float warpSum(float v) {
    #pragma unroll
    for (int o = 16; o; o >>= 1) v += __shfl_xor_sync(0xffffffffu, v, o);
    return v;
}
__device__ __forceinline__ void split2(float x0, float x1, uint32_t& hi, uint32_t& lo) {
    __nv_bfloat162 h = __floats2bfloat162_rn(x0, x1);
    float r0 = x0 - __bfloat162float(h.x);
    float r1 = x1 - __bfloat162float(h.y);
    __nv_bfloat162 l = __floats2bfloat162_rn(r0, r1);
    hi = *(uint32_t*)&h;
    lo = *(uint32_t*)&l;
}
__device__ __forceinline__ void mma_bf16(float* c, const uint32_t* a, const uint32_t* b) {
    asm volatile(
        "mma.sync.aligned.m16n8k16.row.col.f32.bf16.bf16.f32 "
        "{%0,%1,%2,%3}, {%4,%5,%6,%7}, {%8,%9}, {%0,%1,%2,%3};"
        : "+f"(c[0]), "+f"(c[1]), "+f"(c[2]), "+f"(c[3])
        : "r"(a[0]), "r"(a[1]), "r"(a[2]), "r"(a[3]),
          "r"(b[0]), "r"(b[1]));
}
__device__ __forceinline__ void ldsm_x4(uint32_t* r, uint32_t addr) {
    asm volatile("ldmatrix.sync.aligned.m8n8.x4.shared.b16 {%0,%1,%2,%3}, [%4];"
        : "=r"(r[0]), "=r"(r[1]), "=r"(r[2]), "=r"(r[3]) : "r"(addr));
}
__device__ __forceinline__ uint32_t smem_u32(const void* p) {
    uint32_t a;
    asm("{ .reg .u64 t; cvta.to.shared.u64 t, %1; cvt.u32.u64 %0, t; }"
        : "=r"(a) : "l"(p));
    return a;
}
__device__ __forceinline__ void cpa16(uint32_t dst, const void* src) {
    asm volatile("cp.async.cg.shared.global [%0], [%1], 16;"
        :: "r"(dst), "l"(src) : "memory");
}

// ------------------------- weight transpose+split (vectorized) ------------
// W [K][N] fp32 (layer z) -> S [2][N][K/2] packed bf16-pair planes.
// 64x64 tile, float4 loads, uint4 stores.
__global__ void wsplit64(const float* __restrict__ W, uint32_t* __restrict__ S,
                         int K, int N, size_t lsw, size_t lss) {
    const float* Wl = W + (size_t)blockIdx.z * lsw;
    uint32_t*    Sl = S + (size_t)blockIdx.z * lss;
    int k0 = blockIdx.y * 64, n0 = blockIdx.x * 64;
    __shared__ float ts[64][68];
    int tid = threadIdx.x;
    #pragma unroll
    for (int i = 0; i < 4; i++) {
        int e = tid + i * 256;           // float4 index 0..1023
        int r = e >> 4, c4 = e & 15;
        *(float4*)&ts[r][c4 * 4] =
            *(const float4*)(Wl + (size_t)(k0 + r) * N + n0 + c4 * 4);
    }
    __syncthreads();
    size_t pl = (size_t)N * (K >> 1);
    int nn = tid >> 2, seg = (tid & 3) * 8;
    uint32_t hi[8], lo[8];
    #pragma unroll
    for (int j = 0; j < 8; j++) {
        int kp = seg + j;
        split2(ts[2 * kp][nn], ts[2 * kp + 1][nn], hi[j], lo[j]);
    }
    size_t o = (size_t)(n0 + nn) * (K >> 1) + (k0 >> 1) + seg;
    *(uint4*)&Sl[o]        = make_uint4(hi[0], hi[1], hi[2], hi[3]);
    *(uint4*)&Sl[o + 4]    = make_uint4(hi[4], hi[5], hi[6], hi[7]);
    *(uint4*)&Sl[pl + o]     = make_uint4(lo[0], lo[1], lo[2], lo[3]);
    *(uint4*)&Sl[pl + o + 4] = make_uint4(lo[4], lo[5], lo[6], lo[7]);
}

// qkv weights: [L][H][D][HD] -> merged [L][2][3072][512]; sec 0=q,1=k,2=v
__global__ void wsplit_qkv(const float* __restrict__ W, uint32_t* __restrict__ S, int sec) {
    int l = blockIdx.z >> 4, h = blockIdx.z & 15;
    const float* Wl = W + ((size_t)(l * Hc + h)) * Dc * HDc;
    uint32_t*    Sl = S + (size_t)l * 2 * QKVN * (Dc / 2);
    int k0 = blockIdx.y * 64, n0 = blockIdx.x * 32;
    __shared__ float ts[64][33];
    int tid = threadIdx.x;
    #pragma unroll
    for (int i = 0; i < 8; i++) {
        int e = tid + i * 256;
        ts[e >> 5][e & 31] = Wl[(size_t)(k0 + (e >> 5)) * HDc + n0 + (e & 31)];
    }
    __syncthreads();
    size_t pl = (size_t)QKVN * (Dc / 2);
    #pragma unroll
    for (int i = 0; i < 4; i++) {
        int e = tid + i * 256;
        int nn = e >> 5, kp = e & 31;
        uint32_t hi, lo;
        split2(ts[2 * kp][nn], ts[2 * kp + 1][nn], hi, lo);
        int nrow = sec * 1024 + h * HDc + n0 + nn;
        size_t o = (size_t)nrow * (Dc / 2) + (k0 >> 1) + kp;
        Sl[o] = hi; Sl[pl + o] = lo;
    }
}

// ------------------------- embedding gather -------------------------------
__global__ void embed_kernel(const int* __restrict__ idx, const float* __restrict__ emb) {
    int i = blockIdx.x * blockDim.x + threadIdx.x;
    if (i >= BT * Dc) return;
    int row = i >> 10;
    int d   = i & 1023;
    g_x[i] = emb[(size_t)idx[row] * Dc + d];
}

// ------------------------- RMSNorm -> split planes ------------------------
__global__ void rmsnorm_sp(const float* __restrict__ x, const float* __restrict__ w,
                           uint32_t* __restrict__ sp) {
    int row = blockIdx.x, tid = threadIdx.x;
    const float4* xr = (const float4*)(x + (size_t)row * Dc);
    float4 v = xr[tid];
    float ss = v.x*v.x + v.y*v.y + v.z*v.z + v.w*v.w;
    __shared__ float sred[8];
    ss = warpSum(ss);
    if ((tid & 31) == 0) sred[tid >> 5] = ss;
    __syncthreads();
    if (tid == 0) {
        float t = 0.f;
        #pragma unroll
        for (int i = 0; i < 8; i++) t += sred[i];
        sred[0] = rsqrtf(t * (1.0f / Dc) + EPS_RMS);
    }
    __syncthreads();
    float r = sred[0];
    float4 ww = ((const float4*)w)[tid];
    float y0 = v.x*r*ww.x, y1 = v.y*r*ww.y, y2 = v.z*r*ww.z, y3 = v.w*r*ww.w;
    size_t o = (size_t)row * (Dc/2) + tid * 2;
    size_t pl = (size_t)BT * (Dc/2);
    uint32_t hi, lo;
    split2(y0, y1, hi, lo); sp[o]   = hi; sp[pl+o]   = lo;
    split2(y2, y3, hi, lo); sp[o+1] = hi; sp[pl+o+1] = lo;
}

// ------------------------- LayerNorm -> split planes ----------------------
__global__ void layernorm_sp(const float* __restrict__ x, const float* __restrict__ w,
                             const float* __restrict__ b, uint32_t* __restrict__ sp) {
    int row = blockIdx.x, tid = threadIdx.x;
    const float4* xr = (const float4*)(x + (size_t)row * Dc);
    float4 v = xr[tid];
    __shared__ float sred[8];
    __shared__ float sbc[2];
    float s = v.x + v.y + v.z + v.w;
    s = warpSum(s);
    if ((tid & 31) == 0) sred[tid >> 5] = s;
    __syncthreads();
    if (tid == 0) {
        float t = 0.f;
        #pragma unroll
        for (int i = 0; i < 8; i++) t += sred[i];
        sbc[0] = t * (1.0f / Dc);
    }
    __syncthreads();
    float mu = sbc[0];
    float d0 = v.x-mu, d1 = v.y-mu, d2 = v.z-mu, d3 = v.w-mu;
    float sq = d0*d0 + d1*d1 + d2*d2 + d3*d3;
    sq = warpSum(sq);
    if ((tid & 31) == 0) sred[tid >> 5] = sq;
    __syncthreads();
    if (tid == 0) {
        float t = 0.f;
        #pragma unroll
        for (int i = 0; i < 8; i++) t += sred[i];
        sbc[1] = rsqrtf(t * (1.0f / Dc) + EPS_LN);
    }
    __syncthreads();
    float r = sbc[1];
    float4 ww = ((const float4*)w)[tid];
    float4 bb = ((const float4*)b)[tid];
    float y0 = d0*r*ww.x + bb.x, y1 = d1*r*ww.y + bb.y;
    float y2 = d2*r*ww.z + bb.z, y3 = d3*r*ww.w + bb.w;
    size_t o = (size_t)row * (Dc/2) + tid * 2;
    size_t pl = (size_t)BT * (Dc/2);
    uint32_t hi, lo;
    split2(y0, y1, hi, lo); sp[o]   = hi; sp[pl+o]   = lo;
    split2(y2, y3, hi, lo); sp[o+1] = hi; sp[pl+o+1] = lo;
}

// ------------------------- tiled flash attention --------------------------
// grid (T/16, B*H), 256 thr; warp w handles q rows t0+2w, t0+2w+1.
// qkv: [B*T][3072] fp32 (q|k|v). Writes o as split planes [2][BT][Dc/2].
__global__ void __launch_bounds__(256) attn_kernel(const float* __restrict__ qkv,
                                                   uint32_t* __restrict__ osp) {
    __shared__ float Ks[64][68];
    __shared__ float Vs[64][68];
    __shared__ float qs[16][68];
    int tid = threadIdx.x, wid = tid >> 5, lane = tid & 31;
    int bh = blockIdx.y, b = bh >> 4, h = bh & 15;
    int t0 = blockIdx.x << 4;
    int tA = t0 + 2 * wid, tB = tA + 1;
    const float* base = qkv + (size_t)b * Tc * QKVN;

    {   // load 16 q rows
        int r = tid >> 4, c4 = tid & 15;
        const float4* src = (const float4*)(base + (size_t)(t0 + r) * QKVN + h * HDc);
        *(float4*)&qs[r][c4 * 4] = src[c4];
    }

    float mA = -INFINITY, lA = 0.f, oA0 = 0.f, oA1 = 0.f;
    float mB = -INFINITY, lB = 0.f, oB0 = 0.f, oB1 = 0.f;
    int nCh = ((t0 + 15) >> 6) + 1;

    for (int ch = 0; ch < nCh; ch++) {
        int sb = ch << 6;
        __syncthreads();
        #pragma unroll
        for (int i = 0; i < 4; i++) {
            int e = tid + i * 256;
            int r = e >> 4, c4 = e & 15;
            const float* rowp = base + (size_t)(sb + r) * QKVN + h * HDc;
            *(float4*)&Ks[r][c4 * 4] = ((const float4*)(rowp + Dc))[c4];
            *(float4*)&Vs[r][c4 * 4] = ((const float4*)(rowp + 2 * Dc))[c4];
        }
        __syncthreads();

        float sA0 = 0.f, sA1 = 0.f, sB0 = 0.f, sB1 = 0.f;
        const float4* qA4 = (const float4*)qs[2 * wid];
        const float4* qB4 = (const float4*)qs[2 * wid + 1];
        const float4* k40 = (const float4*)Ks[lane];
        const float4* k41 = (const float4*)Ks[lane + 32];
        #pragma unroll
        for (int d = 0; d < 16; d++) {
            float4 ka = k40[d], kb = k41[d];
            float4 qa = qA4[d], qb = qB4[d];
            sA0 += qa.x*ka.x + qa.y*ka.y + qa.z*ka.z + qa.w*ka.w;
            sA1 += qa.x*kb.x + qa.y*kb.y + qa.z*kb.z + qa.w*kb.w;
            sB0 += qb.x*ka.x + qb.y*ka.y + qb.z*ka.z + qb.w*ka.w;
            sB1 += qb.x*kb.x + qb.y*kb.y + qb.z*kb.z + qb.w*kb.w;
        }
        int s0 = sb + lane, s1 = sb + 32 + lane;
        sA0 = (s0 <= tA) ? sA0 * 0.125f : -INFINITY;
        sA1 = (s1 <= tA) ? sA1 * 0.125f : -INFINITY;
        sB0 = (s0 <= tB) ? sB0 * 0.125f : -INFINITY;
        sB1 = (s1 <= tB) ? sB1 * 0.125f : -INFINITY;

        // row A update
        {
            float mch  = warpMax(fmaxf(sA0, sA1));
            float mnew = fmaxf(mA, mch);
            float alpha = __expf(mA - mnew);
            float p0 = __expf(sA0 - mnew);
            float p1 = __expf(sA1 - mnew);
            lA = lA * alpha + warpSum(p0 + p1);
            oA0 *= alpha; oA1 *= alpha;
            mA = mnew;
            sA0 = p0; sA1 = p1;
        }
        // row B update
        {
            float mch  = warpMax(fmaxf(sB0, sB1));
            float mnew = fmaxf(mB, mch);
            float alpha = __expf(mB - mnew);
            float p0 = __expf(sB0 - mnew);
            float p1 = __expf(sB1 - mnew);
            lB = lB * alpha + warpSum(p0 + p1);
            oB0 *= alpha; oB1 *= alpha;
            mB = mnew;
            sB0 = p0; sB1 = p1;
        }
        #pragma unroll
        for (int s = 0; s < 32; s++) {
            float pA = __shfl_sync(0xffffffffu, sA0, s);
            float pB = __shfl_sync(0xffffffffu, sB0, s);
            float2 vv = *(const float2*)&Vs[s][lane * 2];
            oA0 += pA * vv.x; oA1 += pA * vv.y;
            oB0 += pB * vv.x; oB1 += pB * vv.y;
        }
        #pragma unroll
        for (int s = 0; s < 32; s++) {
            float pA = __shfl_sync(0xffffffffu, sA1, s);
            float pB = __shfl_sync(0xffffffffu, sB1, s);
            float2 vv = *(const float2*)&Vs[s + 32][lane * 2];
            oA0 += pA * vv.x; oA1 += pA * vv.y;
            oB0 += pB * vv.x; oB1 += pB * vv.y;
        }
    }

    size_t pl = (size_t)BT * (Dc/2);
    {
        float inv = 1.0f / lA;
        uint32_t hi, lo;
        split2(oA0 * inv, oA1 * inv, hi, lo);
        size_t orow = (size_t)(b * Tc + tA) * (Dc/2) + h * 32 + lane;
        osp[orow] = hi; osp[pl + orow] = lo;
    }
    {
        float inv = 1.0f / lB;
        uint32_t hi, lo;
        split2(oB0 * inv, oB1 * inv, hi, lo);
        size_t orow = (size_t)(b * Tc + tB) * (Dc/2) + h * 32 + lane;
        osp[orow] = hi; osp[pl + orow] = lo;
    }
}

// ------------------------- bf16x3 mma.sync GEMM ---------------------------
// C = A @ B: Asp [2][M][K/2], Bsp [2][N][K/2]. 128x128 tile, BK=32,
// 3-stage cp.async pipeline, ldmatrix fragments, 8 warps (4m x 2n).
#define F_F32  1
#define F_RES  2
#define F_SPL  4
#define F_SILU 8
#define OP_AH 0
#define OP_AL 8192
#define OP_BH 16384
#define OP_BL 24576
#define STGB  32768
#define GEMM_SMEM (3*STGB)

__device__ __forceinline__ uint32_t swz_addr(int row, int c) {
    return (uint32_t)(row * 64 + ((c * 16) ^ (((row >> 1) & 3) << 4)));
}

__global__ void __launch_bounds__(256, 2) tc_gemm(
    const uint32_t* __restrict__ Asp, const uint32_t* __restrict__ Bsp,
    const float* __restrict__ bias, float* __restrict__ Cf,
    uint32_t* __restrict__ Csp, const uint32_t* __restrict__ AuxSp,
    int M, int N, int K, int flags)
{
    extern __shared__ char smem[];
    uint32_t smem0 = smem_u32(smem);
    int tid = threadIdx.x, wid = tid >> 5, lane = tid & 31;
    int m0 = blockIdx.y << 7, n0 = blockIdx.x << 7;
    int Kh = K >> 1;
    size_t planeA = (size_t)M * Kh, planeB = (size_t)N * Kh;
    const uint32_t* Ag = Asp + (size_t)m0 * Kh;
    const uint32_t* Bg = Bsp + (size_t)n0 * Kh;
    int nCh = K >> 5;

    int r0 = tid >> 2, c0 = tid & 3;
    int r1 = r0 + 64;

    auto load_st = [&](int ch, int st) {
        uint32_t sb = smem0 + st * STGB;
        int kofs = ch * 16 + c0 * 4;
        const uint32_t* a0 = Ag + (size_t)r0 * Kh + kofs;
        const uint32_t* a1 = Ag + (size_t)r1 * Kh + kofs;
        const uint32_t* b0 = Bg + (size_t)r0 * Kh + kofs;
        const uint32_t* b1 = Bg + (size_t)r1 * Kh + kofs;
        uint32_t s0 = swz_addr(r0, c0), s1 = swz_addr(r1, c0);
        cpa16(sb + OP_AH + s0, a0);
        cpa16(sb + OP_AH + s1, a1);
        cpa16(sb + OP_AL + s0, a0 + planeA);
        cpa16(sb + OP_AL + s1, a1 + planeA);
        cpa16(sb + OP_BH + s0, b0);
        cpa16(sb + OP_BH + s1, b1);
        cpa16(sb + OP_BL + s0, b0 + planeB);
        cpa16(sb + OP_BL + s1, b1 + planeB);
        asm volatile("cp.async.commit_group;" ::: "memory");
    };

    float acc[2][8][4];
    #pragma unroll
    for (int i = 0; i < 2; i++)
        #pragma unroll
        for (int j = 0; j < 8; j++)
            #pragma unroll
            for (int r = 0; r < 4; r++) acc[i][j][r] = 0.f;

    int wm = (wid & 3) << 5, wn = (wid >> 2) << 6;
    int lrow = lane & 15, lhalf = lane >> 4;

    load_st(0, 0);
    load_st(1, 1);

    for (int ch = 0; ch < nCh; ch++) {
        if (ch + 2 < nCh) {
            asm volatile("cp.async.wait_group 1;" ::: "memory");
        } else {
            asm volatile("cp.async.wait_group 0;" ::: "memory");
        }
        __syncthreads();
        uint32_t sb = smem0 + (ch % 3) * STGB;
        #pragma unroll
        for (int ks = 0; ks < 2; ks++) {
            int c = ks * 2 + lhalf;
            uint32_t ah[2][4], al[2][4], bq[4][4];
            #pragma unroll
            for (int i = 0; i < 2; i++) {
                int row = wm + i * 16 + lrow;
                uint32_t sa = swz_addr(row, c);
                ldsm_x4(ah[i], sb + OP_AH + sa);
                ldsm_x4(al[i], sb + OP_AL + sa);
            }
            #pragma unroll
            for (int jj = 0; jj < 4; jj++)
                ldsm_x4(bq[jj], sb + OP_BH + swz_addr(wn + jj * 16 + lrow, c));
            #pragma unroll
            for (int jj = 0; jj < 4; jj++) {
                uint32_t bf0[2] = {bq[jj][0], bq[jj][2]};
                uint32_t bf1[2] = {bq[jj][1], bq[jj][3]};
                #pragma unroll
                for (int i = 0; i < 2; i++) {
                    mma_bf16(acc[i][2*jj],   ah[i], bf0);
                    mma_bf16(acc[i][2*jj+1], ah[i], bf1);
                    mma_bf16(acc[i][2*jj],   al[i], bf0);
                    mma_bf16(acc[i][2*jj+1], al[i], bf1);
                }
            }
            #pragma unroll
            for (int jj = 0; jj < 4; jj++)
                ldsm_x4(bq[jj], sb + OP_BL + swz_addr(wn + jj * 16 + lrow, c));
            #pragma unroll
            for (int jj = 0; jj < 4; jj++) {
                uint32_t bf0[2] = {bq[jj][0], bq[jj][2]};
                uint32_t bf1[2] = {bq[jj][1], bq[jj][3]};
                #pragma unroll
                for (int i = 0; i < 2; i++) {
                    mma_bf16(acc[i][2*jj],   ah[i], bf0);
                    mma_bf16(acc[i][2*jj+1], ah[i], bf1);
                }
            }
        }
        if (ch + 2 < nCh) load_st(ch + 2, (ch + 2) % 3);
    }

    // epilogue
    int erow = lane >> 2;
    int ecol = (lane & 3) * 2;
    size_t splPl = (size_t)M * (N >> 1);
    #pragma unroll
    for (int i = 0; i < 2; i++) {
        int row = m0 + wm + i * 16 + erow;
        #pragma unroll
        for (int j = 0; j < 8; j++) {
            int col = n0 + wn + j * 8 + ecol;
            float b0 = 0.f, b1 = 0.f;
            if (bias) { b0 = bias[col]; b1 = bias[col + 1]; }
            float v00 = acc[i][j][0] + b0, v01 = acc[i][j][1] + b1;
            float v10 = acc[i][j][2] + b0, v11 = acc[i][j][3] + b1;
            size_t o0 = (size_t)row * N + col;
            size_t o1 = (size_t)(row + 8) * N + col;
            size_t p0 = (size_t)row * (N >> 1) + (col >> 1);
            size_t p1 = (size_t)(row + 8) * (N >> 1) + (col >> 1);
            if (flags & F_SILU) {
                // reconstruct pre-activation a from its split planes, apply silu
                __nv_bfloat162 h0 = *(const __nv_bfloat162*)&AuxSp[p0];
                __nv_bfloat162 l0 = *(const __nv_bfloat162*)&AuxSp[splPl + p0];
                __nv_bfloat162 h1 = *(const __nv_bfloat162*)&AuxSp[p1];
                __nv_bfloat162 l1 = *(const __nv_bfloat162*)&AuxSp[splPl + p1];
                float a00 = __bfloat162float(h0.x) + __bfloat162float(l0.x);
                float a01 = __bfloat162float(h0.y) + __bfloat162float(l0.y);
                float a10 = __bfloat162float(h1.x) + __bfloat162float(l1.x);
                float a11 = __bfloat162float(h1.y) + __bfloat162float(l1.y);
                v00 *= a00 / (1.0f + expf(-a00));
                v01 *= a01 / (1.0f + expf(-a01));
                v10 *= a10 / (1.0f + expf(-a10));
                v11 *= a11 / (1.0f + expf(-a11));
            }
            if (flags & F_RES) {
                v00 += Cf[o0]; v01 += Cf[o0 + 1];
                v10 += Cf[o1]; v11 += Cf[o1 + 1];
            }
            if (flags & F_F32) {
                Cf[o0] = v00; Cf[o0 + 1] = v01;
                Cf[o1] = v10; Cf[o1 + 1] = v11;
            }
            if (flags & F_SPL) {
                uint32_t hi, lo;
                split2(v00, v01, hi, lo); Csp[p0] = hi; Csp[splPl + p0] = lo;
                split2(v10, v11, hi, lo); Csp[p1] = hi; Csp[splPl + p1] = lo;
            }
        }
    }
}

// ------------------------- host orchestration -----------------------------
extern "C" void kernel_launch(void* const* d_in, const int* in_sizes, int n_in,
                              void* d_out, int out_size) {
    const int*   idx    = (const int*)  d_in[0];
    const float* emb    = (const float*)d_in[1];
    const float* wq     = (const float*)d_in[2];
    const float* wk     = (const float*)d_in[3];
    const float* wv     = (const float*)d_in[4];
    const float* attn_w = (const float*)d_in[5];
    const float* attn_b = (const float*)d_in[6];
    const float* n1_w   = (const float*)d_in[7];
    const float* n2_w   = (const float*)d_in[8];
    const float* f1_w   = (const float*)d_in[9];
    const float* f1_b   = (const float*)d_in[10];
    const float* fs_w   = (const float*)d_in[11];
    const float* fs_b   = (const float*)d_in[12];
    const float* f2_w   = (const float*)d_in[13];
    const float* f2_b   = (const float*)d_in[14];
    const float* ln_w   = (const float*)d_in[15];
    const float* ln_b   = (const float*)d_in[16];
    const float* out_w  = (const float*)d_in[17];
    const float* out_b  = (const float*)d_in[18];

    float *x, *qkv;
    uint32_t *hsp, *osp, *asp, *msp;
    uint32_t *swqkv, *swo, *sf1, *sfs, *sf2, *sout;
    cudaGetSymbolAddress((void**)&x,    g_x);
    cudaGetSymbolAddress((void**)&qkv,  g_qkv);
    cudaGetSymbolAddress((void**)&hsp,  g_hsp);
    cudaGetSymbolAddress((void**)&osp,  g_osp);
    cudaGetSymbolAddress((void**)&asp,  g_asp);
    cudaGetSymbolAddress((void**)&msp,  g_msp);
    cudaGetSymbolAddress((void**)&swqkv,g_swqkv);
    cudaGetSymbolAddress((void**)&swo,  g_swo);
    cudaGetSymbolAddress((void**)&sf1,  g_sf1);
    cudaGetSymbolAddress((void**)&sfs,  g_sfs);
    cudaGetSymbolAddress((void**)&sf2,  g_sf2);
    cudaGetSymbolAddress((void**)&sout, g_sout);

    cudaFuncSetAttribute(tc_gemm,
                         cudaFuncAttributeMaxDynamicSharedMemorySize, GEMM_SMEM);

    dim3 gQKV(QKVN/128, BT/128);
    dim3 gD(Dc/128, BT/128);
    dim3 gF(FFc/128, BT/128);
    dim3 gV(Vc/128, BT/128);

    embed_kernel<<<(BT * Dc) / 256, 256>>>(idx, emb);
    wsplit_qkv<<<dim3(2, 16, Lc * Hc), 256>>>(wq, swqkv, 0);
    wsplit_qkv<<<dim3(2, 16, Lc * Hc), 256>>>(wk, swqkv, 1);
    wsplit_qkv<<<dim3(2, 16, Lc * Hc), 256>>>(wv, swqkv, 2);
    rmsnorm_sp<<<BT, 256>>>(x, n1_w, hsp);
    tc_gemm<<<gQKV, 256, GEMM_SMEM>>>(hsp, swqkv, nullptr, qkv, nullptr,
                                      nullptr, BT, QKVN, Dc, F_F32);

    // remaining weight splits (vectorized 64x64)
    wsplit64<<<dim3(Dc/64,  Dc/64,  Lc), 256>>>(attn_w, swo, Dc,  Dc,
        (size_t)Dc*Dc,   (size_t)2*Dc*(Dc/2));
    wsplit64<<<dim3(FFc/64, Dc/64,  Lc), 256>>>(f1_w,   sf1, Dc,  FFc,
        (size_t)Dc*FFc,  (size_t)2*FFc*(Dc/2));
    wsplit64<<<dim3(FFc/64, FFc/64, Lc), 256>>>(fs_w,   sfs, FFc, FFc,
        (size_t)FFc*FFc, (size_t)2*FFc*(FFc/2));
    wsplit64<<<dim3(Dc/64,  FFc/64, Lc), 256>>>(f2_w,   sf2, FFc, Dc,
        (size_t)FFc*Dc,  (size_t)2*Dc*(FFc/2));
    wsplit64<<<dim3(Vc/64,  Dc/64,  1),  256>>>(out_w,  sout, Dc, Vc, 0, 0);

    for (int l = 0; l < Lc; l++) {
        uint32_t* wqkv_l = swqkv + (size_t)l * 2 * QKVN * (Dc/2);
        uint32_t* swo_l  = swo   + (size_t)l * 2 * Dc   * (Dc/2);
        uint32_t* sf1_l  = sf1   + (size_t)l * 2 * FFc  * (Dc/2);
        uint32_t* sfs_l  = sfs   + (size_t)l * 2 * FFc  * (FFc/2);
        uint32_t* sf2_l  = sf2   + (size_t)l * 2 * Dc   * (FFc/2);

        if (l > 0) {
            rmsnorm_sp<<<BT, 256>>>(x, n1_w + (size_t)l * Dc, hsp);
            tc_gemm<<<gQKV, 256, GEMM_SMEM>>>(hsp, wqkv_l, nullptr, qkv,
                                              nullptr, nullptr, BT, QKVN, Dc, F_F32);
        }
        // rope diagonal is all-ones (theta = x // HD == 0): K unchanged.
        attn_kernel<<<dim3(Tc/16, Bc*Hc), 256>>>(qkv, osp);
        tc_gemm<<<gD, 256, GEMM_SMEM>>>(osp, swo_l, attn_b + (size_t)l * Dc,
                                        x, nullptr, nullptr, BT, Dc, Dc,
                                        F_F32 | F_RES);

        rmsnorm_sp<<<BT, 256>>>(x, n2_w + (size_t)l * Dc, hsp);
        tc_gemm<<<gF, 256, GEMM_SMEM>>>(hsp, sf1_l, f1_b + (size_t)l * FFc,
                                        nullptr, asp, nullptr, BT, FFc, Dc,
                                        F_SPL);
        tc_gemm<<<gF, 256, GEMM_SMEM>>>(asp, sfs_l, fs_b + (size_t)l * FFc,
                                        nullptr, msp, asp, BT, FFc, FFc,
                                        F_SPL | F_SILU);
        tc_gemm<<<gD, 256, GEMM_SMEM>>>(msp, sf2_l, f2_b + (size_t)l * Dc,
                                        x, nullptr, nullptr, BT, Dc, FFc,
                                        F_F32 | F_RES);
    }

    layernorm_sp<<<BT, 256>>>(x, ln_w, ln_b, hsp);
    tc_gemm<<<gV, 256, GEMM_SMEM>>>(hsp, sout, out_b, (float*)d_out, nullptr,
                                    nullptr, BT, Vc, Dc, F_F32);
}

// round 17
// speedup vs baseline: 1.1154x; 1.0110x over previous
#include <cuda_runtime.h>
#include <cuda_bf16.h>
#include <math.h>
#include <stdint.h>

// Problem constants
#define Bc   2
#define Tc   1024
#define Dc   1024
#define Hc   16
#define HDc  64
#define FFc  4096
#define Lc   2
#define Vc   32000
#define BT   (Bc*Tc)
#define QKVN 3072

#define EPS_RMS 1.1920929e-07f
#define EPS_LN  1e-5f

// ------------------------- device scratch (static, no allocs) -------------
__device__ float    g_x  [BT*Dc];
__device__ float    g_qkv[BT*QKVN];
// split-plane activations: [2][rows][K/2] packed bf16 k-pairs
__device__ uint32_t g_hsp[2*BT*(Dc/2)];
__device__ uint32_t g_osp[2*BT*(Dc/2)];
__device__ uint32_t g_asp[2*BT*(FFc/2)];
__device__ uint32_t g_msp[2*BT*(FFc/2)];
// split weights: [L][2][N][K/2]
__device__ uint32_t g_swqkv[(size_t)Lc*2*QKVN*(Dc/2)];
__device__ uint32_t g_swo  [(size_t)Lc*2*Dc*(Dc/2)];
__device__ uint32_t g_sf1  [(size_t)Lc*2*FFc*(Dc/2)];
__device__ uint32_t g_sfs  [(size_t)Lc*2*FFc*(FFc/2)];
__device__ uint32_t g_sf2  [(size_t)Lc*2*Dc*(FFc/2)];
__device__ uint32_t g_sout [(size_t)2*Vc*(Dc/2)];

// ------------------------- helpers ---------------------------------------
__device__ __forceinline__ float warpMax(float v) {
    #pragma unroll
    for (int o = 16; o; o >>= 1) v = fmaxf(v, __shfl_xor_sync(0xffffffffu, v, o));
    return v;
}
__device__ __forceinline__ float warpSum(float v) {
    #pragma unroll
    for (int o = 16; o; o >>= 1) v += __shfl_xor_sync(0xffffffffu, v, o);
    return v;
}
__device__ __forceinline__ void split2(float x0, float x1, uint32_t& hi, uint32_t& lo) {
    __nv_bfloat162 h = __floats2bfloat162_rn(x0, x1);
    float r0 = x0 - __bfloat162float(h.x);
    float r1 = x1 - __bfloat162float(h.y);
    __nv_bfloat162 l = __floats2bfloat162_rn(r0, r1);
    hi = *(uint32_t*)&h;
    lo = *(uint32_t*)&l;
}
__device__ __forceinline__ void mma_bf16(float* c, const uint32_t* a, const uint32_t* b) {
    asm volatile(
        "mma.sync.aligned.m16n8k16.row.col.f32.bf16.bf16.f32 "
        "{%0,%1,%2,%3}, {%4,%5,%6,%7}, {%8,%9}, {%0,%1,%2,%3};"
        : "+f"(c[0]), "+f"(c[1]), "+f"(c[2]), "+f"(c[3])
        : "r"(a[0]), "r"(a[1]), "r"(a[2]), "r"(a[3]),
          "r"(b[0]), "r"(b[1]));
}
__device__ __forceinline__ void ldsm_x4(uint32_t* r, uint32_t addr) {
    asm volatile("ldmatrix.sync.aligned.m8n8.x4.shared.b16 {%0,%1,%2,%3}, [%4];"
        : "=r"(r[0]), "=r"(r[1]), "=r"(r[2]), "=r"(r[3]) : "r"(addr));
}
__device__ __forceinline__ uint32_t smem_u32(const void* p) {
    uint32_t a;
    asm("{ .reg .u64 t; cvta.to.shared.u64 t, %1; cvt.u32.u64 %0, t; }"
        : "=r"(a) : "l"(p));
    return a;
}
__device__ __forceinline__ void cpa16(uint32_t dst, const void* src) {
    asm volatile("cp.async.cg.shared.global [%0], [%1], 16;"
        :: "r"(dst), "l"(src) : "memory");
}

// ------------------------- weight transpose+split (vectorized) ------------
// W [K][N] fp32 (layer z) -> S [2][N][K/2] packed bf16-pair planes.
// 64x64 tile, float4 loads, uint4 stores.
__global__ void wsplit64(const float* __restrict__ W, uint32_t* __restrict__ S,
                         int K, int N, size_t lsw, size_t lss) {
    const float* Wl = W + (size_t)blockIdx.z * lsw;
    uint32_t*    Sl = S + (size_t)blockIdx.z * lss;
    int k0 = blockIdx.y * 64, n0 = blockIdx.x * 64;
    __shared__ float ts[64][68];
    int tid = threadIdx.x;
    #pragma unroll
    for (int i = 0; i < 4; i++) {
        int e = tid + i * 256;           // float4 index 0..1023
        int r = e >> 4, c4 = e & 15;
        *(float4*)&ts[r][c4 * 4] =
            *(const float4*)(Wl + (size_t)(k0 + r) * N + n0 + c4 * 4);
    }
    __syncthreads();
    size_t pl = (size_t)N * (K >> 1);
    int nn = tid >> 2, seg = (tid & 3) * 8;
    uint32_t hi[8], lo[8];
    #pragma unroll
    for (int j = 0; j < 8; j++) {
        int kp = seg + j;
        split2(ts[2 * kp][nn], ts[2 * kp + 1][nn], hi[j], lo[j]);
    }
    size_t o = (size_t)(n0 + nn) * (K >> 1) + (k0 >> 1) + seg;
    *(uint4*)&Sl[o]        = make_uint4(hi[0], hi[1], hi[2], hi[3]);
    *(uint4*)&Sl[o + 4]    = make_uint4(hi[4], hi[5], hi[6], hi[7]);
    *(uint4*)&Sl[pl + o]     = make_uint4(lo[0], lo[1], lo[2], lo[3]);
    *(uint4*)&Sl[pl + o + 4] = make_uint4(lo[4], lo[5], lo[6], lo[7]);
}

// qkv weights: [L][H][D][HD] -> merged [L][2][3072][512]; sec 0=q,1=k,2=v
__global__ void wsplit_qkv(const float* __restrict__ W, uint32_t* __restrict__ S, int sec) {
    int l = blockIdx.z >> 4, h = blockIdx.z & 15;
    const float* Wl = W + ((size_t)(l * Hc + h)) * Dc * HDc;
    uint32_t*    Sl = S + (size_t)l * 2 * QKVN * (Dc / 2);
    int k0 = blockIdx.y * 64, n0 = blockIdx.x * 32;
    __shared__ float ts[64][33];
    int tid = threadIdx.x;
    #pragma unroll
    for (int i = 0; i < 8; i++) {
        int e = tid + i * 256;
        ts[e >> 5][e & 31] = Wl[(size_t)(k0 + (e >> 5)) * HDc + n0 + (e & 31)];
    }
    __syncthreads();
    size_t pl = (size_t)QKVN * (Dc / 2);
    #pragma unroll
    for (int i = 0; i < 4; i++) {
        int e = tid + i * 256;
        int nn = e >> 5, kp = e & 31;
        uint32_t hi, lo;
        split2(ts[2 * kp][nn], ts[2 * kp + 1][nn], hi, lo);
        int nrow = sec * 1024 + h * HDc + n0 + nn;
        size_t o = (size_t)nrow * (Dc / 2) + (k0 >> 1) + kp;
        Sl[o] = hi; Sl[pl + o] = lo;
    }
}

// ------------------------- embedding gather -------------------------------
__global__ void embed_kernel(const int* __restrict__ idx, const float* __restrict__ emb) {
    int i = blockIdx.x * blockDim.x + threadIdx.x;
    if (i >= BT * Dc) return;
    int row = i >> 10;
    int d   = i & 1023;
    g_x[i] = emb[(size_t)idx[row] * Dc + d];
}

// ------------------------- RMSNorm -> split planes ------------------------
__global__ void rmsnorm_sp(const float* __restrict__ x, const float* __restrict__ w,
                           uint32_t* __restrict__ sp) {
    int row = blockIdx.x, tid = threadIdx.x;
    const float4* xr = (const float4*)(x + (size_t)row * Dc);
    float4 v = xr[tid];
    float ss = v.x*v.x + v.y*v.y + v.z*v.z + v.w*v.w;
    __shared__ float sred[8];
    ss = warpSum(ss);
    if ((tid & 31) == 0) sred[tid >> 5] = ss;
    __syncthreads();
    if (tid == 0) {
        float t = 0.f;
        #pragma unroll
        for (int i = 0; i < 8; i++) t += sred[i];
        sred[0] = rsqrtf(t * (1.0f / Dc) + EPS_RMS);
    }
    __syncthreads();
    float r = sred[0];
    float4 ww = ((const float4*)w)[tid];
    float y0 = v.x*r*ww.x, y1 = v.y*r*ww.y, y2 = v.z*r*ww.z, y3 = v.w*r*ww.w;
    size_t o = (size_t)row * (Dc/2) + tid * 2;
    size_t pl = (size_t)BT * (Dc/2);
    uint32_t hi, lo;
    split2(y0, y1, hi, lo); sp[o]   = hi; sp[pl+o]   = lo;
    split2(y2, y3, hi, lo); sp[o+1] = hi; sp[pl+o+1] = lo;
}

// ------------------------- LayerNorm -> split planes ----------------------
__global__ void layernorm_sp(const float* __restrict__ x, const float* __restrict__ w,
                             const float* __restrict__ b, uint32_t* __restrict__ sp) {
    int row = blockIdx.x, tid = threadIdx.x;
    const float4* xr = (const float4*)(x + (size_t)row * Dc);
    float4 v = xr[tid];
    __shared__ float sred[8];
    __shared__ float sbc[2];
    float s = v.x + v.y + v.z + v.w;
    s = warpSum(s);
    if ((tid & 31) == 0) sred[tid >> 5] = s;
    __syncthreads();
    if (tid == 0) {
        float t = 0.f;
        #pragma unroll
        for (int i = 0; i < 8; i++) t += sred[i];
        sbc[0] = t * (1.0f / Dc);
    }
    __syncthreads();
    float mu = sbc[0];
    float d0 = v.x-mu, d1 = v.y-mu, d2 = v.z-mu, d3 = v.w-mu;
    float sq = d0*d0 + d1*d1 + d2*d2 + d3*d3;
    sq = warpSum(sq);
    if ((tid & 31) == 0) sred[tid >> 5] = sq;
    __syncthreads();
    if (tid == 0) {
        float t = 0.f;
        #pragma unroll
        for (int i = 0; i < 8; i++) t += sred[i];
        sbc[1] = rsqrtf(t * (1.0f / Dc) + EPS_LN);
    }
    __syncthreads();
    float r = sbc[1];
    float4 ww = ((const float4*)w)[tid];
    float4 bb = ((const float4*)b)[tid];
    float y0 = d0*r*ww.x + bb.x, y1 = d1*r*ww.y + bb.y;
    float y2 = d2*r*ww.z + bb.z, y3 = d3*r*ww.w + bb.w;
    size_t o = (size_t)row * (Dc/2) + tid * 2;
    size_t pl = (size_t)BT * (Dc/2);
    uint32_t hi, lo;
    split2(y0, y1, hi, lo); sp[o]   = hi; sp[pl+o]   = lo;
    split2(y2, y3, hi, lo); sp[o+1] = hi; sp[pl+o+1] = lo;
}

// ------------------------- tiled flash attention --------------------------
// grid (T/16, B*H), 256 thr; warp w handles q rows t0+2w, t0+2w+1.
// qkv: [B*T][3072] fp32 (q|k|v). Writes o as split planes [2][BT][Dc/2].
__global__ void __launch_bounds__(256) attn_kernel(const float* __restrict__ qkv,
                                                   uint32_t* __restrict__ osp) {
    __shared__ float Ks[64][68];
    __shared__ float Vs[64][68];
    __shared__ float qs[16][68];
    int tid = threadIdx.x, wid = tid >> 5, lane = tid & 31;
    int bh = blockIdx.y, b = bh >> 4, h = bh & 15;
    int t0 = blockIdx.x << 4;
    int tA = t0 + 2 * wid, tB = tA + 1;
    const float* base = qkv + (size_t)b * Tc * QKVN;

    {   // load 16 q rows
        int r = tid >> 4, c4 = tid & 15;
        const float4* src = (const float4*)(base + (size_t)(t0 + r) * QKVN + h * HDc);
        *(float4*)&qs[r][c4 * 4] = src[c4];
    }

    float mA = -INFINITY, lA = 0.f, oA0 = 0.f, oA1 = 0.f;
    float mB = -INFINITY, lB = 0.f, oB0 = 0.f, oB1 = 0.f;
    int nCh = ((t0 + 15) >> 6) + 1;

    for (int ch = 0; ch < nCh; ch++) {
        int sb = ch << 6;
        __syncthreads();
        #pragma unroll
        for (int i = 0; i < 4; i++) {
            int e = tid + i * 256;
            int r = e >> 4, c4 = e & 15;
            const float* rowp = base + (size_t)(sb + r) * QKVN + h * HDc;
            *(float4*)&Ks[r][c4 * 4] = ((const float4*)(rowp + Dc))[c4];
            *(float4*)&Vs[r][c4 * 4] = ((const float4*)(rowp + 2 * Dc))[c4];
        }
        __syncthreads();

        float sA0 = 0.f, sA1 = 0.f, sB0 = 0.f, sB1 = 0.f;
        const float4* qA4 = (const float4*)qs[2 * wid];
        const float4* qB4 = (const float4*)qs[2 * wid + 1];
        const float4* k40 = (const float4*)Ks[lane];
        const float4* k41 = (const float4*)Ks[lane + 32];
        #pragma unroll
        for (int d = 0; d < 16; d++) {
            float4 ka = k40[d], kb = k41[d];
            float4 qa = qA4[d], qb = qB4[d];
            sA0 += qa.x*ka.x + qa.y*ka.y + qa.z*ka.z + qa.w*ka.w;
            sA1 += qa.x*kb.x + qa.y*kb.y + qa.z*kb.z + qa.w*kb.w;
            sB0 += qb.x*ka.x + qb.y*ka.y + qb.z*ka.z + qb.w*ka.w;
            sB1 += qb.x*kb.x + qb.y*kb.y + qb.z*kb.z + qb.w*kb.w;
        }
        int s0 = sb + lane, s1 = sb + 32 + lane;
        sA0 = (s0 <= tA) ? sA0 * 0.125f : -INFINITY;
        sA1 = (s1 <= tA) ? sA1 * 0.125f : -INFINITY;
        sB0 = (s0 <= tB) ? sB0 * 0.125f : -INFINITY;
        sB1 = (s1 <= tB) ? sB1 * 0.125f : -INFINITY;

        // row A update
        {
            float mch  = warpMax(fmaxf(sA0, sA1));
            float mnew = fmaxf(mA, mch);
            float alpha = __expf(mA - mnew);
            float p0 = __expf(sA0 - mnew);
            float p1 = __expf(sA1 - mnew);
            lA = lA * alpha + warpSum(p0 + p1);
            oA0 *= alpha; oA1 *= alpha;
            mA = mnew;
            sA0 = p0; sA1 = p1;
        }
        // row B update
        {
            float mch  = warpMax(fmaxf(sB0, sB1));
            float mnew = fmaxf(mB, mch);
            float alpha = __expf(mB - mnew);
            float p0 = __expf(sB0 - mnew);
            float p1 = __expf(sB1 - mnew);
            lB = lB * alpha + warpSum(p0 + p1);
            oB0 *= alpha; oB1 *= alpha;
            mB = mnew;
            sB0 = p0; sB1 = p1;
        }
        #pragma unroll
        for (int s = 0; s < 32; s++) {
            float pA = __shfl_sync(0xffffffffu, sA0, s);
            float pB = __shfl_sync(0xffffffffu, sB0, s);
            float2 vv = *(const float2*)&Vs[s][lane * 2];
            oA0 += pA * vv.x; oA1 += pA * vv.y;
            oB0 += pB * vv.x; oB1 += pB * vv.y;
        }
        #pragma unroll
        for (int s = 0; s < 32; s++) {
            float pA = __shfl_sync(0xffffffffu, sA1, s);
            float pB = __shfl_sync(0xffffffffu, sB1, s);
            float2 vv = *(const float2*)&Vs[s + 32][lane * 2];
            oA0 += pA * vv.x; oA1 += pA * vv.y;
            oB0 += pB * vv.x; oB1 += pB * vv.y;
        }
    }

    size_t pl = (size_t)BT * (Dc/2);
    {
        float inv = 1.0f / lA;
        uint32_t hi, lo;
        split2(oA0 * inv, oA1 * inv, hi, lo);
        size_t orow = (size_t)(b * Tc + tA) * (Dc/2) + h * 32 + lane;
        osp[orow] = hi; osp[pl + orow] = lo;
    }
    {
        float inv = 1.0f / lB;
        uint32_t hi, lo;
        split2(oB0 * inv, oB1 * inv, hi, lo);
        size_t orow = (size_t)(b * Tc + tB) * (Dc/2) + h * 32 + lane;
        osp[orow] = hi; osp[pl + orow] = lo;
    }
}

// ------------------------- bf16x3 mma.sync GEMM ---------------------------
// C = A @ B: Asp [2][M][K/2], Bsp [2][N][K/2]. 128x128 tile, BK=32,
// 3-stage cp.async pipeline, ldmatrix fragments, 8 warps (4m x 2n).
#define F_F32  1
#define F_RES  2
#define F_SPL  4
#define F_SILU 8
#define OP_AH 0
#define OP_AL 8192
#define OP_BH 16384
#define OP_BL 24576
#define STGB  32768
#define GEMM_SMEM (3*STGB)

__device__ __forceinline__ uint32_t swz_addr(int row, int c) {
    return (uint32_t)(row * 64 + ((c * 16) ^ (((row >> 1) & 3) << 4)));
}

__global__ void __launch_bounds__(256, 2) tc_gemm(
    const uint32_t* __restrict__ Asp, const uint32_t* __restrict__ Bsp,
    const float* __restrict__ bias, float* __restrict__ Cf,
    uint32_t* __restrict__ Csp, const uint32_t* __restrict__ AuxSp,
    int M, int N, int K, int flags)
{
    extern __shared__ char smem[];
    uint32_t smem0 = smem_u32(smem);
    int tid = threadIdx.x, wid = tid >> 5, lane = tid & 31;
    int m0 = blockIdx.y << 7, n0 = blockIdx.x << 7;
    int Kh = K >> 1;
    size_t planeA = (size_t)M * Kh, planeB = (size_t)N * Kh;
    const uint32_t* Ag = Asp + (size_t)m0 * Kh;
    const uint32_t* Bg = Bsp + (size_t)n0 * Kh;
    int nCh = K >> 5;

    int r0 = tid >> 2, c0 = tid & 3;
    int r1 = r0 + 64;

    auto load_st = [&](int ch, int st) {
        uint32_t sb = smem0 + st * STGB;
        int kofs = ch * 16 + c0 * 4;
        const uint32_t* a0 = Ag + (size_t)r0 * Kh + kofs;
        const uint32_t* a1 = Ag + (size_t)r1 * Kh + kofs;
        const uint32_t* b0 = Bg + (size_t)r0 * Kh + kofs;
        const uint32_t* b1 = Bg + (size_t)r1 * Kh + kofs;
        uint32_t s0 = swz_addr(r0, c0), s1 = swz_addr(r1, c0);
        cpa16(sb + OP_AH + s0, a0);
        cpa16(sb + OP_AH + s1, a1);
        cpa16(sb + OP_AL + s0, a0 + planeA);
        cpa16(sb + OP_AL + s1, a1 + planeA);
        cpa16(sb + OP_BH + s0, b0);
        cpa16(sb + OP_BH + s1, b1);
        cpa16(sb + OP_BL + s0, b0 + planeB);
        cpa16(sb + OP_BL + s1, b1 + planeB);
        asm volatile("cp.async.commit_group;" ::: "memory");
    };

    float acc[2][8][4];
    #pragma unroll
    for (int i = 0; i < 2; i++)
        #pragma unroll
        for (int j = 0; j < 8; j++)
            #pragma unroll
            for (int r = 0; r < 4; r++) acc[i][j][r] = 0.f;

    int wm = (wid & 3) << 5, wn = (wid >> 2) << 6;
    int lrow = lane & 15, lhalf = lane >> 4;

    load_st(0, 0);
    load_st(1, 1);

    for (int ch = 0; ch < nCh; ch++) {
        if (ch + 2 < nCh) {
            asm volatile("cp.async.wait_group 1;" ::: "memory");
        } else {
            asm volatile("cp.async.wait_group 0;" ::: "memory");
        }
        __syncthreads();
        uint32_t sb = smem0 + (ch % 3) * STGB;
        #pragma unroll
        for (int ks = 0; ks < 2; ks++) {
            int c = ks * 2 + lhalf;
            uint32_t ah[2][4], al[2][4], bq[4][4];
            #pragma unroll
            for (int i = 0; i < 2; i++) {
                int row = wm + i * 16 + lrow;
                uint32_t sa = swz_addr(row, c);
                ldsm_x4(ah[i], sb + OP_AH + sa);
                ldsm_x4(al[i], sb + OP_AL + sa);
            }
            #pragma unroll
            for (int jj = 0; jj < 4; jj++)
                ldsm_x4(bq[jj], sb + OP_BH + swz_addr(wn + jj * 16 + lrow, c));
            #pragma unroll
            for (int jj = 0; jj < 4; jj++) {
                uint32_t bf0[2] = {bq[jj][0], bq[jj][2]};
                uint32_t bf1[2] = {bq[jj][1], bq[jj][3]};
                #pragma unroll
                for (int i = 0; i < 2; i++) {
                    mma_bf16(acc[i][2*jj],   ah[i], bf0);
                    mma_bf16(acc[i][2*jj+1], ah[i], bf1);
                    mma_bf16(acc[i][2*jj],   al[i], bf0);
                    mma_bf16(acc[i][2*jj+1], al[i], bf1);
                }
            }
            #pragma unroll
            for (int jj = 0; jj < 4; jj++)
                ldsm_x4(bq[jj], sb + OP_BL + swz_addr(wn + jj * 16 + lrow, c));
            #pragma unroll
            for (int jj = 0; jj < 4; jj++) {
                uint32_t bf0[2] = {bq[jj][0], bq[jj][2]};
                uint32_t bf1[2] = {bq[jj][1], bq[jj][3]};
                #pragma unroll
                for (int i = 0; i < 2; i++) {
                    mma_bf16(acc[i][2*jj],   ah[i], bf0);
                    mma_bf16(acc[i][2*jj+1], ah[i], bf1);
                }
            }
        }
        if (ch + 2 < nCh) load_st(ch + 2, (ch + 2) % 3);
    }

    // epilogue
    int erow = lane >> 2;
    int ecol = (lane & 3) * 2;
    size_t splPl = (size_t)M * (N >> 1);
    #pragma unroll
    for (int i = 0; i < 2; i++) {
        int row = m0 + wm + i * 16 + erow;
        #pragma unroll
        for (int j = 0; j < 8; j++) {
            int col = n0 + wn + j * 8 + ecol;
            float b0 = 0.f, b1 = 0.f;
            if (bias) { b0 = bias[col]; b1 = bias[col + 1]; }
            float v00 = acc[i][j][0] + b0, v01 = acc[i][j][1] + b1;
            float v10 = acc[i][j][2] + b0, v11 = acc[i][j][3] + b1;
            size_t o0 = (size_t)row * N + col;
            size_t o1 = (size_t)(row + 8) * N + col;
            size_t p0 = (size_t)row * (N >> 1) + (col >> 1);
            size_t p1 = (size_t)(row + 8) * (N >> 1) + (col >> 1);
            if (flags & F_SILU) {
                // reconstruct pre-activation a from its split planes, apply silu
                __nv_bfloat162 h0 = *(const __nv_bfloat162*)&AuxSp[p0];
                __nv_bfloat162 l0 = *(const __nv_bfloat162*)&AuxSp[splPl + p0];
                __nv_bfloat162 h1 = *(const __nv_bfloat162*)&AuxSp[p1];
                __nv_bfloat162 l1 = *(const __nv_bfloat162*)&AuxSp[splPl + p1];
                float a00 = __bfloat162float(h0.x) + __bfloat162float(l0.x);
                float a01 = __bfloat162float(h0.y) + __bfloat162float(l0.y);
                float a10 = __bfloat162float(h1.x) + __bfloat162float(l1.x);
                float a11 = __bfloat162float(h1.y) + __bfloat162float(l1.y);
                v00 *= a00 / (1.0f + expf(-a00));
                v01 *= a01 / (1.0f + expf(-a01));
                v10 *= a10 / (1.0f + expf(-a10));
                v11 *= a11 / (1.0f + expf(-a11));
            }
            if (flags & F_RES) {
                v00 += Cf[o0]; v01 += Cf[o0 + 1];
                v10 += Cf[o1]; v11 += Cf[o1 + 1];
            }
            if (flags & F_F32) {
                Cf[o0] = v00; Cf[o0 + 1] = v01;
                Cf[o1] = v10; Cf[o1 + 1] = v11;
            }
            if (flags & F_SPL) {
                uint32_t hi, lo;
                split2(v00, v01, hi, lo); Csp[p0] = hi; Csp[splPl + p0] = lo;
                split2(v10, v11, hi, lo); Csp[p1] = hi; Csp[splPl + p1] = lo;
            }
        }
    }
}

// ------------------------- host orchestration -----------------------------
extern "C" void kernel_launch(void* const* d_in, const int* in_sizes, int n_in,
                              void* d_out, int out_size) {
    const int*   idx    = (const int*)  d_in[0];
    const float* emb    = (const float*)d_in[1];
    const float* wq     = (const float*)d_in[2];
    const float* wk     = (const float*)d_in[3];
    const float* wv     = (const float*)d_in[4];
    const float* attn_w = (const float*)d_in[5];
    const float* attn_b = (const float*)d_in[6];
    const float* n1_w   = (const float*)d_in[7];
    const float* n2_w   = (const float*)d_in[8];
    const float* f1_w   = (const float*)d_in[9];
    const float* f1_b   = (const float*)d_in[10];
    const float* fs_w   = (const float*)d_in[11];
    const float* fs_b   = (const float*)d_in[12];
    const float* f2_w   = (const float*)d_in[13];
    const float* f2_b   = (const float*)d_in[14];
    const float* ln_w   = (const float*)d_in[15];
    const float* ln_b   = (const float*)d_in[16];
    const float* out_w  = (const float*)d_in[17];
    const float* out_b  = (const float*)d_in[18];

    float *x, *qkv;
    uint32_t *hsp, *osp, *asp, *msp;
    uint32_t *swqkv, *swo, *sf1, *sfs, *sf2, *sout;
    cudaGetSymbolAddress((void**)&x,    g_x);
    cudaGetSymbolAddress((void**)&qkv,  g_qkv);
    cudaGetSymbolAddress((void**)&hsp,  g_hsp);
    cudaGetSymbolAddress((void**)&osp,  g_osp);
    cudaGetSymbolAddress((void**)&asp,  g_asp);
    cudaGetSymbolAddress((void**)&msp,  g_msp);
    cudaGetSymbolAddress((void**)&swqkv,g_swqkv);
    cudaGetSymbolAddress((void**)&swo,  g_swo);
    cudaGetSymbolAddress((void**)&sf1,  g_sf1);
    cudaGetSymbolAddress((void**)&sfs,  g_sfs);
    cudaGetSymbolAddress((void**)&sf2,  g_sf2);
    cudaGetSymbolAddress((void**)&sout, g_sout);

    cudaFuncSetAttribute(tc_gemm,
                         cudaFuncAttributeMaxDynamicSharedMemorySize, GEMM_SMEM);

    dim3 gQKV(QKVN/128, BT/128);
    dim3 gD(Dc/128, BT/128);
    dim3 gF(FFc/128, BT/128);
    dim3 gV(Vc/128, BT/128);

    embed_kernel<<<(BT * Dc) / 256, 256>>>(idx, emb);
    wsplit_qkv<<<dim3(2, 16, Lc * Hc), 256>>>(wq, swqkv, 0);
    wsplit_qkv<<<dim3(2, 16, Lc * Hc), 256>>>(wk, swqkv, 1);
    wsplit_qkv<<<dim3(2, 16, Lc * Hc), 256>>>(wv, swqkv, 2);
    rmsnorm_sp<<<BT, 256>>>(x, n1_w, hsp);
    tc_gemm<<<gQKV, 256, GEMM_SMEM>>>(hsp, swqkv, nullptr, qkv, nullptr,
                                      nullptr, BT, QKVN, Dc, F_F32);

    // remaining weight splits (vectorized 64x64)
    wsplit64<<<dim3(Dc/64,  Dc/64,  Lc), 256>>>(attn_w, swo, Dc,  Dc,
        (size_t)Dc*Dc,   (size_t)2*Dc*(Dc/2));
    wsplit64<<<dim3(FFc/64, Dc/64,  Lc), 256>>>(f1_w,   sf1, Dc,  FFc,
        (size_t)Dc*FFc,  (size_t)2*FFc*(Dc/2));
    wsplit64<<<dim3(FFc/64, FFc/64, Lc), 256>>>(fs_w,   sfs, FFc, FFc,
        (size_t)FFc*FFc, (size_t)2*FFc*(FFc/2));
    wsplit64<<<dim3(Dc/64,  FFc/64, Lc), 256>>>(f2_w,   sf2, FFc, Dc,
        (size_t)FFc*Dc,  (size_t)2*Dc*(FFc/2));
    wsplit64<<<dim3(Vc/64,  Dc/64,  1),  256>>>(out_w,  sout, Dc, Vc, 0, 0);

    for (int l = 0; l < Lc; l++) {
        uint32_t* wqkv_l = swqkv + (size_t)l * 2 * QKVN * (Dc/2);
        uint32_t* swo_l  = swo   + (size_t)l * 2 * Dc   * (Dc/2);
        uint32_t* sf1_l  = sf1   + (size_t)l * 2 * FFc  * (Dc/2);
        uint32_t* sfs_l  = sfs   + (size_t)l * 2 * FFc  * (FFc/2);
        uint32_t* sf2_l  = sf2   + (size_t)l * 2 * Dc   * (FFc/2);

        if (l > 0) {
            rmsnorm_sp<<<BT, 256>>>(x, n1_w + (size_t)l * Dc, hsp);
            tc_gemm<<<gQKV, 256, GEMM_SMEM>>>(hsp, wqkv_l, nullptr, qkv,
                                              nullptr, nullptr, BT, QKVN, Dc, F_F32);
        }
        // rope diagonal is all-ones (theta = x // HD == 0): K unchanged.
        attn_kernel<<<dim3(Tc/16, Bc*Hc), 256>>>(qkv, osp);
        tc_gemm<<<gD, 256, GEMM_SMEM>>>(osp, swo_l, attn_b + (size_t)l * Dc,
                                        x, nullptr, nullptr, BT, Dc, Dc,
                                        F_F32 | F_RES);

        rmsnorm_sp<<<BT, 256>>>(x, n2_w + (size_t)l * Dc, hsp);
        tc_gemm<<<gF, 256, GEMM_SMEM>>>(hsp, sf1_l, f1_b + (size_t)l * FFc,
                                        nullptr, asp, nullptr, BT, FFc, Dc,
                                        F_SPL);
        tc_gemm<<<gF, 256, GEMM_SMEM>>>(asp, sfs_l, fs_b + (size_t)l * FFc,
                                        nullptr, msp, asp, BT, FFc, FFc,
                                        F_SPL | F_SILU);
        tc_gemm<<<gD, 256, GEMM_SMEM>>>(msp, sf2_l, f2_b + (size_t)l * Dc,
                                        x, nullptr, nullptr, BT, Dc, FFc,
                                        F_F32 | F_RES);
    }

    layernorm_sp<<<BT, 256>>>(x, ln_w, ln_b, hsp);
    tc_gemm<<<gV, 256, GEMM_SMEM>>>(hsp, sout, out_b, (float*)d_out, nullptr,
                                    nullptr, BT, Vc, Dc, F_F32);
}